// round 4
// baseline (speedup 1.0000x reference)
#include <cuda_runtime.h>
#include <math.h>

#define BATCH   16
#define DMODEL  4096
#define NH      32
#define NKV     8
#define DK      128
#define GQ      4
#define MAXBLK  256
#define SPLITS  8
#define TT      32          // tokens per attention tile (double-buffered)
#define KSPLIT  4
#define KT      64
#define RT      32          // rows per GEMM CTA
#define ROWS_QKV 6144
#define ROWS_O   4096

typedef unsigned long long u64;

#define FMA2(acc, w, x) asm("fma.rn.f32x2 %0, %1, %2, %0;" : "+l"(acc) : "l"(w), "l"(x))
#define MUL2(d, a, b)   asm("mul.rn.f32x2 %0, %1, %2;"     : "=l"(d)  : "l"(a), "l"(b))
#define CP16(dst, src)  asm volatile("cp.async.cg.shared.global [%0], [%1], 16;" :: "r"(dst), "l"(src))
#define CPCOMMIT()      asm volatile("cp.async.commit_group;")
#define CPWAIT(n)       asm volatile("cp.async.wait_group %0;" :: "n"(n))

__device__ __forceinline__ unsigned sptr(const void* p) {
    return (unsigned)__cvta_generic_to_shared(p);
}

// ---------------- scratch ----------------------------------------------------
// partials layout: part[(row*16 + b)*4 + ksplit]  (4 ksplits contiguous = float4)
__device__ float g_part_qkv[ROWS_QKV * BATCH * KSPLIT];
__device__ float g_part_o  [ROWS_O   * BATCH * KSPLIT];
__device__ float g_att[BATCH * DMODEL];
__device__ float g_po [BATCH * NKV * SPLITS * GQ * DK];
__device__ float g_pm [BATCH * NKV * SPLITS * GQ];
__device__ float g_pl [BATCH * NKV * SPLITS * GQ];

// ============ GEMM: 32 rows/CTA x 16 batches, k-split, f32x2 =================
// 128 thr = 4 warps; warp owns 8 rows. lane = (i = lane>>4, b = lane&15);
// lane accumulates 4 row-pairs (rows wid*8 + 2j + i) for batch b.
__global__ __launch_bounds__(128, 6) void gemm_k(
    const float* __restrict__ WQ, const float* __restrict__ WK,
    const float* __restrict__ WV, const float* __restrict__ x,
    float* __restrict__ part)
{
    __shared__ __align__(16) float ws[2][RT][68];
    __shared__ __align__(16) float xs[2][16][68];

    const int tid  = threadIdx.x;
    const int lane = tid & 31;
    const int wid  = tid >> 5;
    const int rowBase = blockIdx.x * RT;
    const int k0      = blockIdx.y * (DMODEL / KSPLIT);

    const float* W; int wr;
    if (rowBase < 4096)      { W = WQ; wr = rowBase; }
    else if (rowBase < 5120) { W = WK; wr = rowBase - 4096; }
    else                     { W = WV; wr = rowBase - 5120; }

    const unsigned wsA = sptr(&ws[0][0][0]);
    const unsigned xsA = sptr(&xs[0][0][0]);

    const int wrow_t = tid >> 4;        // 0..7
    const int wcol_t = (tid & 15) * 4;  // 0..60
    const float* wsrc0 = W + (size_t)wr * DMODEL + k0 + wcol_t;

    #define ISSUE(c, buf) do {                                                 \
        const float* wp = wsrc0 + (c) * KT;                                    \
        _Pragma("unroll")                                                      \
        for (int s = 0; s < 4; s++) {                                          \
            int r = wrow_t + s * 8;                                            \
            CP16(wsA + (((buf) * RT + r) * 68 + wcol_t) * 4,                   \
                 wp + (size_t)r * DMODEL);                                     \
        }                                                                      \
        {                                                                      \
            int idx = tid;                                                     \
            int bb = idx >> 4, kq = (idx & 15) * 4;                            \
            CP16(xsA + (((buf) * 16 + bb) * 68 + kq) * 4,                      \
                 x + (size_t)bb * DMODEL + k0 + (c) * KT + kq);                \
            idx = tid + 128;                                                   \
            bb = idx >> 4; kq = (idx & 15) * 4;                                \
            CP16(xsA + (((buf) * 16 + bb) * 68 + kq) * 4,                      \
                 x + (size_t)bb * DMODEL + k0 + (c) * KT + kq);                \
        }                                                                      \
        CPCOMMIT();                                                            \
    } while (0)

    u64 acc[4];
#pragma unroll
    for (int j = 0; j < 4; j++) acc[j] = 0ull;

    const int i = lane >> 4;
    const int b = lane & 15;
    const int NC = (DMODEL / KSPLIT) / KT;   // 16

    ISSUE(0, 0);
    for (int c = 0; c < NC; c++) {
        if (c + 1 < NC) { ISSUE(c + 1, (c + 1) & 1); CPWAIT(1); }
        else            { CPWAIT(0); }
        __syncthreads();
        const int buf = c & 1;
        const float* wrow0 = &ws[buf][wid * 8 + i][0];
        const float* xrow  = &xs[buf][b][0];
#pragma unroll
        for (int k4 = 0; k4 < KT; k4 += 4) {
            ulonglong2 xv = *(const ulonglong2*)(xrow + k4);
#pragma unroll
            for (int j = 0; j < 4; j++) {
                ulonglong2 wv = *(const ulonglong2*)(wrow0 + (2 * j) * 68 + k4);
                FMA2(acc[j], wv.x, xv.x);
                FMA2(acc[j], wv.y, xv.y);
            }
        }
        __syncthreads();
    }
#pragma unroll
    for (int j = 0; j < 4; j++) {
        int row = rowBase + wid * 8 + 2 * j + i;
        float2 f = *(float2*)&acc[j];
        part[((size_t)row * BATCH + b) * KSPLIT + blockIdx.y] = f.x + f.y;
    }
    #undef ISSUE
}

// ============ flash-decode attention (reduces its own q/k/v + rope) ==========
__global__ __launch_bounds__(256, 3) void attn_kernel(
    const float* __restrict__ k_pool, const float* __restrict__ v_pool,
    const int* __restrict__ positions, const int* __restrict__ block_table)
{
    __shared__ __align__(16) float Vs[2][TT][DK];
    __shared__ __align__(16) float qs[GQ * DK];
    __shared__ __align__(16) float kn[DK];
    __shared__ __align__(16) float vn[DK];
    __shared__ float  ss [GQ][TT];
    __shared__ __align__(8) float2 psd[GQ][TT];
    __shared__ float  salpha[GQ];

    const int split = blockIdx.x, h = blockIdx.y, b = blockIdx.z;
    const int tid = threadIdx.x, lane = tid & 31, wid = tid >> 5;

    const int pos = positions[b];
    const int seq = pos + 1;
    const int chunk = (seq + SPLITS - 1) / SPLITS;
    const int s0 = split * chunk;
    const int s1 = min(s0 + chunk, seq);
    const int NT = (s1 > s0) ? ((s1 - s0 + TT - 1) / TT) : 0;

    const unsigned VsA = sptr(&Vs[0][0][0]);
    int offs[4];
    float4 ka[4], kb[4];

    #define TBL(ti) do {                                                       \
        int t0_ = s0 + (ti) * TT;                                              \
        _Pragma("unroll")                                                      \
        for (int jj = 0; jj < 4; jj++) {                                       \
            int j = wid * 4 + jj, gt = t0_ + j;                                \
            offs[jj] = (gt < s1)                                               \
                ? ((block_table[b * MAXBLK + (gt >> 4)] * 16 + (gt & 15))      \
                   * NKV + h) * DK                                             \
                : -1;                                                          \
        }                                                                      \
    } while (0)

    #define KLOAD(dst) do {                                                    \
        _Pragma("unroll")                                                      \
        for (int jj = 0; jj < 4; jj++)                                         \
            if (offs[jj] >= 0)                                                 \
                dst[jj] = *(const float4*)(k_pool + (size_t)offs[jj] + lane*4);\
    } while (0)

    #define VISSUE(buf) do {                                                   \
        _Pragma("unroll")                                                      \
        for (int jj = 0; jj < 4; jj++) {                                       \
            int j = wid * 4 + jj;                                              \
            if (offs[jj] >= 0)                                                 \
                CP16(VsA + (((buf) * TT + j) * DK + lane * 4) * 4,             \
                     v_pool + (size_t)offs[jj] + lane * 4);                    \
        }                                                                      \
        CPCOMMIT();                                                            \
    } while (0)

    // kick off tile 0 loads before the prologue compute
    if (NT > 0) { TBL(0); KLOAD(ka); VISSUE(0); if (NT > 1) TBL(1); }

    // ---- prologue: reduce ksplit partials + rope for q, k_new, v_new ----
    {
        const float4* p4 = (const float4*)g_part_qkv;
        const float fpos = (float)pos;
        // q: each thread one rotation pair
        int hl = tid >> 6, d = tid & 63;
        int rowlo = (h * GQ + hl) * DK + d;
        float4 plo = p4[rowlo * BATCH + b];
        float4 phi = p4[(rowlo + 64) * BATCH + b];
        float lo = plo.x + plo.y + plo.z + plo.w;
        float hi = phi.x + phi.y + phi.z + phi.w;
        float inv = exp2f(-(float)d * 0.2076205059304601f);
        float sn, cs;
        sincosf(fpos * inv, &sn, &cs);
        qs[hl * DK + d]      = lo * cs - hi * sn;
        qs[hl * DK + d + 64] = hi * cs + lo * sn;
        if (tid < 64) {                      // k_new rotation pairs
            int rk = 4096 + h * DK + tid;
            float4 qlo = p4[rk * BATCH + b];
            float4 qhi = p4[(rk + 64) * BATCH + b];
            float klo = qlo.x + qlo.y + qlo.z + qlo.w;
            float khi = qhi.x + qhi.y + qhi.z + qhi.w;
            float inv2 = exp2f(-(float)tid * 0.2076205059304601f);
            float sn2, cs2;
            sincosf(fpos * inv2, &sn2, &cs2);
            kn[tid]      = klo * cs2 - khi * sn2;
            kn[tid + 64] = khi * cs2 + klo * sn2;
        } else if (tid < 192) {              // v_new
            int dv = tid - 64;
            float4 pv = p4[(5120 + h * DK + dv) * BATCH + b];
            vn[dv] = pv.x + pv.y + pv.z + pv.w;
        }
    }
    __syncthreads();

    const float4 q0 = *(const float4*)&qs[0 * DK + lane * 4];
    const float4 q1 = *(const float4*)&qs[1 * DK + lane * 4];
    const float4 q2 = *(const float4*)&qs[2 * DK + lane * 4];
    const float4 q3 = *(const float4*)&qs[3 * DK + lane * 4];

    const float scale = 0.08838834764831845f;
    float m_run = -INFINITY, l_run = 0.f;
    const int g2 = tid >> 6;
    const int d0 = (tid & 63) * 2;
    u64 o2 = 0ull;

    for (int ti = 0; ti < NT; ti++) {
        const int t0 = s0 + ti * TT;
        const int nv = min(s1 - t0, TT);
        const int buf = ti & 1;

        if (ti + 1 < NT) { KLOAD(kb); VISSUE((ti + 1) & 1); }
        if (ti + 2 < NT) TBL(ti + 2);
        if (ti + 1 < NT) CPWAIT(1); else CPWAIT(0);

        // substitute new-token V (pool slot holds stale data)
        int jp = pos - t0;
        if (jp >= 0 && jp < nv && tid < 32)
            *(float4*)&Vs[buf][jp][tid * 4] = *(const float4*)&vn[tid * 4];
        __syncthreads();

        // ---- scores (warp's 4 tokens, K from prefetched regs) ----
#pragma unroll
        for (int jj = 0; jj < 4; jj++) {
            int j = wid * 4 + jj;
            if (j < nv) {
                float4 kv = ka[jj];
                if (t0 + j == pos) kv = *(const float4*)&kn[lane * 4];
                float p0 = kv.x * q0.x + kv.y * q0.y + kv.z * q0.z + kv.w * q0.w;
                float p1 = kv.x * q1.x + kv.y * q1.y + kv.z * q1.z + kv.w * q1.w;
                float p2 = kv.x * q2.x + kv.y * q2.y + kv.z * q2.z + kv.w * q2.w;
                float p3 = kv.x * q3.x + kv.y * q3.y + kv.z * q3.z + kv.w * q3.w;
#pragma unroll
                for (int offv = 16; offv; offv >>= 1) {
                    p0 += __shfl_xor_sync(0xffffffffu, p0, offv);
                    p1 += __shfl_xor_sync(0xffffffffu, p1, offv);
                    p2 += __shfl_xor_sync(0xffffffffu, p2, offv);
                    p3 += __shfl_xor_sync(0xffffffffu, p3, offv);
                }
                if (lane == 0) {
                    ss[0][j] = p0 * scale;
                    ss[1][j] = p1 * scale;
                    ss[2][j] = p2 * scale;
                    ss[3][j] = p3 * scale;
                }
            }
        }
        __syncthreads();
        // ---- online softmax (warps 0..3, one per g) ----
        if (wid < 4) {
            int g = wid;
            float v0 = (lane < nv) ? ss[g][lane] : -INFINITY;
            float mt = v0;
#pragma unroll
            for (int offv = 16; offv; offv >>= 1)
                mt = fmaxf(mt, __shfl_xor_sync(0xffffffffu, mt, offv));
            float m_new = fmaxf(m_run, mt);
            float alpha = __expf(m_run - m_new);
            float e0 = __expf(v0 - m_new);
            psd[g][lane] = make_float2(e0, e0);
            float sum = e0;
#pragma unroll
            for (int offv = 16; offv; offv >>= 1)
                sum += __shfl_xor_sync(0xffffffffu, sum, offv);
            l_run = l_run * alpha + sum;
            m_run = m_new;
            if (lane == 0) salpha[g] = alpha;
        }
        __syncthreads();
        // ---- packed O accumulation ----
        {
            float a = salpha[g2];
            float2 ad = make_float2(a, a);
            u64 a2 = *(u64*)&ad;
            u64 t;
            MUL2(t, o2, a2);
            o2 = t;
#pragma unroll 4
            for (int j = 0; j < nv; j++) {
                u64 v = *(const u64*)&Vs[buf][j][d0];
                u64 p = *(const u64*)&psd[g2][j];
                FMA2(o2, p, v);
            }
        }
        __syncthreads();
        // rotate prefetched K regs
#pragma unroll
        for (int jj = 0; jj < 4; jj++) ka[jj] = kb[jj];
    }

    const int pidx = (b * NKV + h) * SPLITS + split;
    float2 of = *(float2*)&o2;
    g_po[pidx * (GQ * DK) + g2 * DK + d0]     = of.x;
    g_po[pidx * (GQ * DK) + g2 * DK + d0 + 1] = of.y;
    if (wid < 4 && lane == 0) {
        g_pm[pidx * GQ + wid] = m_run;
        g_pl[pidx * GQ + wid] = l_run;
    }
    #undef TBL
    #undef KLOAD
    #undef VISSUE
}

// ============ combine split partials -> g_att (1 thread / elem) ==============
__global__ void combine_kernel()
{
    int id = blockIdx.x * 128 + threadIdx.x;   // 65536
    int d = id & 127;
    int g = (id >> 7) & 3;
    int h = (id >> 9) & 7;
    int b = id >> 12;
    int base = (b * NKV + h) * SPLITS;
    float M = -INFINITY;
#pragma unroll
    for (int s = 0; s < SPLITS; s++)
        M = fmaxf(M, g_pm[(base + s) * GQ + g]);
    float L = 0.f, o = 0.f;
#pragma unroll
    for (int s = 0; s < SPLITS; s++) {
        float e = __expf(g_pm[(base + s) * GQ + g] - M);
        L += g_pl[(base + s) * GQ + g] * e;
        o += e * g_po[(base + s) * (GQ * DK) + g * DK + d];
    }
    g_att[b * DMODEL + (h * GQ + g) * DK + d] = o / L;
}

// ============ reduce O partials -> d_out =====================================
__global__ void reduce_o(float* __restrict__ out)
{
    int id = blockIdx.x * 256 + threadIdx.x;   // 65536
    int b = id >> 12;
    int r = id & 4095;
    float4 v = ((const float4*)g_part_o)[r * BATCH + b];
    out[(size_t)b * DMODEL + r] = v.x + v.y + v.z + v.w;
}

// ---------------- host launcher ---------------------------------------------
extern "C" void kernel_launch(void* const* d_in, const int* in_sizes, int n_in,
                              void* d_out, int out_size)
{
    const float* hs = (const float*)d_in[0];
    const float* WQ = (const float*)d_in[1];
    const float* WK = (const float*)d_in[2];
    const float* WV = (const float*)d_in[3];
    const float* WO = (const float*)d_in[4];
    const float* kp = (const float*)d_in[5];
    const float* vp = (const float*)d_in[6];
    const int*   ps = (const int*)d_in[7];
    const int*   bt = (const int*)d_in[8];
    float* out = (float*)d_out;

    float *gatt, *partQ, *partO;
    cudaGetSymbolAddress((void**)&gatt,  g_att);
    cudaGetSymbolAddress((void**)&partQ, g_part_qkv);
    cudaGetSymbolAddress((void**)&partO, g_part_o);

    gemm_k<<<dim3(ROWS_QKV / RT, KSPLIT), 128>>>(WQ, WK, WV, hs, partQ);
    attn_kernel<<<dim3(SPLITS, NKV, BATCH), 256>>>(kp, vp, ps, bt);
    combine_kernel<<<512, 128>>>();
    gemm_k<<<dim3(ROWS_O / RT, KSPLIT), 128>>>(WO, WO, WO, gatt, partO);
    reduce_o<<<256, 256>>>(out);
}

// round 5
// speedup vs baseline: 1.1099x; 1.1099x over previous
#include <cuda_runtime.h>
#include <math.h>

#define BATCH   16
#define DMODEL  4096
#define NH      32
#define NKV     8
#define DK      128
#define GQ      4
#define MAXBLK  256
#define SPLITS  8
#define TT      32          // tokens per attention tile (double-buffered)
#define KSPLIT  4
#define KT      64
#define RT      32          // rows per GEMM CTA
#define NSTAGE  4
#define ROWS_QKV 6144
#define ROWS_O   4096

typedef unsigned long long u64;

#define FMA2(acc, w, x) asm("fma.rn.f32x2 %0, %1, %2, %0;" : "+l"(acc) : "l"(w), "l"(x))
#define MUL2(d, a, b)   asm("mul.rn.f32x2 %0, %1, %2;"     : "=l"(d)  : "l"(a), "l"(b))
#define CP16(dst, src)  asm volatile("cp.async.cg.shared.global [%0], [%1], 16;" :: "r"(dst), "l"(src))
#define CPCOMMIT()      asm volatile("cp.async.commit_group;")
#define CPWAIT(n)       asm volatile("cp.async.wait_group %0;" :: "n"(n))

__device__ __forceinline__ unsigned sptr(const void* p) {
    return (unsigned)__cvta_generic_to_shared(p);
}

// ---------------- scratch ----------------------------------------------------
// partials layout: part[(row*16 + b)*4 + ksplit]  (4 ksplits contiguous = float4)
__device__ float g_part_qkv[ROWS_QKV * BATCH * KSPLIT];
__device__ float g_part_o  [ROWS_O   * BATCH * KSPLIT];
__device__ float g_att[BATCH * DMODEL];
__device__ float g_po [BATCH * NKV * SPLITS * GQ * DK];
__device__ float g_pm [BATCH * NKV * SPLITS * GQ];
__device__ float g_pl [BATCH * NKV * SPLITS * GQ];

// ============ GEMM: 32 rows/CTA x 16 batches, 4-stage pipeline, f32x2 ========
// 128 thr = 4 warps; warp owns 8 rows. lane = (i = lane>>4, b = lane&15);
// lane accumulates 4 row-pairs (rows wid*8 + 2j + i) for batch b.
__global__ __launch_bounds__(128, 4) void gemm_k(
    const float* __restrict__ WQ, const float* __restrict__ WK,
    const float* __restrict__ WV, const float* __restrict__ x,
    float* __restrict__ part)
{
    __shared__ __align__(16) float ws[NSTAGE][RT][68];
    __shared__ __align__(16) float xs[NSTAGE][16][68];

    const int tid  = threadIdx.x;
    const int lane = tid & 31;
    const int wid  = tid >> 5;
    const int rowBase = blockIdx.x * RT;
    const int k0      = blockIdx.y * (DMODEL / KSPLIT);

    const float* W; int wr;
    if (rowBase < 4096)      { W = WQ; wr = rowBase; }
    else if (rowBase < 5120) { W = WK; wr = rowBase - 4096; }
    else                     { W = WV; wr = rowBase - 5120; }

    const unsigned wsA = sptr(&ws[0][0][0]);
    const unsigned xsA = sptr(&xs[0][0][0]);

    const int wrow_t = tid >> 4;        // 0..7
    const int wcol_t = (tid & 15) * 4;  // 0..60
    const float* wsrc0 = W + (size_t)wr * DMODEL + k0 + wcol_t;

    #define ISSUE(c) do {                                                      \
        int buf_ = (c) & (NSTAGE - 1);                                         \
        const float* wp = wsrc0 + (c) * KT;                                    \
        _Pragma("unroll")                                                      \
        for (int s = 0; s < 4; s++) {                                          \
            int r = wrow_t + s * 8;                                            \
            CP16(wsA + ((buf_ * RT + r) * 68 + wcol_t) * 4,                    \
                 wp + (size_t)r * DMODEL);                                     \
        }                                                                      \
        {                                                                      \
            int idx = tid;                                                     \
            int bb = idx >> 4, kq = (idx & 15) * 4;                            \
            CP16(xsA + ((buf_ * 16 + bb) * 68 + kq) * 4,                       \
                 x + (size_t)bb * DMODEL + k0 + (c) * KT + kq);                \
            idx = tid + 128;                                                   \
            bb = idx >> 4; kq = (idx & 15) * 4;                                \
            CP16(xsA + ((buf_ * 16 + bb) * 68 + kq) * 4,                       \
                 x + (size_t)bb * DMODEL + k0 + (c) * KT + kq);                \
        }                                                                      \
        CPCOMMIT();                                                            \
    } while (0)

    u64 acc[4];
#pragma unroll
    for (int j = 0; j < 4; j++) acc[j] = 0ull;

    const int i = lane >> 4;
    const int b = lane & 15;
    const int NC = (DMODEL / KSPLIT) / KT;   // 16

    ISSUE(0); ISSUE(1); ISSUE(2);
    for (int c = 0; c < NC; c++) {
        int rem = NC - 1 - c;                // groups issued after chunk c
        if (rem >= 2)      CPWAIT(2);
        else if (rem == 1) CPWAIT(1);
        else               CPWAIT(0);
        __syncthreads();
        if (c + 3 < NC) ISSUE(c + 3);        // fills buffer (c-1)&3, safe
        const int buf = c & (NSTAGE - 1);
        const float* wrow0 = &ws[buf][wid * 8 + i][0];
        const float* xrow  = &xs[buf][b][0];
#pragma unroll
        for (int k4 = 0; k4 < KT; k4 += 4) {
            ulonglong2 xv = *(const ulonglong2*)(xrow + k4);
#pragma unroll
            for (int j = 0; j < 4; j++) {
                ulonglong2 wv = *(const ulonglong2*)(wrow0 + (2 * j) * 68 + k4);
                FMA2(acc[j], wv.x, xv.x);
                FMA2(acc[j], wv.y, xv.y);
            }
        }
        __syncthreads();
    }
#pragma unroll
    for (int j = 0; j < 4; j++) {
        int row = rowBase + wid * 8 + 2 * j + i;
        float2 f = *(float2*)&acc[j];
        part[((size_t)row * BATCH + b) * KSPLIT + blockIdx.y] = f.x + f.y;
    }
    #undef ISSUE
}

// ============ flash-decode attention (reduces its own q/k/v + rope) ==========
__global__ __launch_bounds__(256, 2) void attn_kernel(
    const float* __restrict__ k_pool, const float* __restrict__ v_pool,
    const int* __restrict__ positions, const int* __restrict__ block_table)
{
    __shared__ __align__(16) float Vs[2][TT][DK];
    __shared__ __align__(16) float qs[GQ * DK];
    __shared__ __align__(16) float kn[DK];
    __shared__ __align__(16) float vn[DK];
    __shared__ float  ss [GQ][TT];
    __shared__ __align__(8) float2 psd[GQ][TT];
    __shared__ float  salpha[GQ];

    const int split = blockIdx.x, h = blockIdx.y, b = blockIdx.z;
    const int tid = threadIdx.x, lane = tid & 31, wid = tid >> 5;

    const int pos = positions[b];
    const int seq = pos + 1;
    const int chunk = (seq + SPLITS - 1) / SPLITS;
    const int s0 = split * chunk;
    const int s1 = min(s0 + chunk, seq);
    const int NT = (s1 > s0) ? ((s1 - s0 + TT - 1) / TT) : 0;

    const unsigned VsA = sptr(&Vs[0][0][0]);
    int offs[4];
    float4 ka[4], kb[4];

    #define TBL(ti) do {                                                       \
        int t0_ = s0 + (ti) * TT;                                              \
        _Pragma("unroll")                                                      \
        for (int jj = 0; jj < 4; jj++) {                                       \
            int j = wid * 4 + jj, gt = t0_ + j;                                \
            offs[jj] = (gt < s1)                                               \
                ? ((block_table[b * MAXBLK + (gt >> 4)] * 16 + (gt & 15))      \
                   * NKV + h) * DK                                             \
                : -1;                                                          \
        }                                                                      \
    } while (0)

    #define KLOAD(dst) do {                                                    \
        _Pragma("unroll")                                                      \
        for (int jj = 0; jj < 4; jj++)                                         \
            if (offs[jj] >= 0)                                                 \
                dst[jj] = *(const float4*)(k_pool + (size_t)offs[jj] + lane*4);\
    } while (0)

    #define VISSUE(buf) do {                                                   \
        _Pragma("unroll")                                                      \
        for (int jj = 0; jj < 4; jj++) {                                       \
            int j = wid * 4 + jj;                                              \
            if (offs[jj] >= 0)                                                 \
                CP16(VsA + (((buf) * TT + j) * DK + lane * 4) * 4,             \
                     v_pool + (size_t)offs[jj] + lane * 4);                    \
        }                                                                      \
        CPCOMMIT();                                                            \
    } while (0)

    // kick off tile 0 loads before the prologue compute
    if (NT > 0) { TBL(0); KLOAD(ka); VISSUE(0); if (NT > 1) TBL(1); }

    // ---- prologue: reduce ksplit partials + rope for q, k_new, v_new ----
    {
        const float4* p4 = (const float4*)g_part_qkv;
        const float fpos = (float)pos;
        int hl = tid >> 6, d = tid & 63;
        int rowlo = (h * GQ + hl) * DK + d;
        float4 plo = p4[rowlo * BATCH + b];
        float4 phi = p4[(rowlo + 64) * BATCH + b];
        float lo = plo.x + plo.y + plo.z + plo.w;
        float hi = phi.x + phi.y + phi.z + phi.w;
        float inv = exp2f(-(float)d * 0.2076205059304601f);
        float sn, cs;
        sincosf(fpos * inv, &sn, &cs);
        qs[hl * DK + d]      = lo * cs - hi * sn;
        qs[hl * DK + d + 64] = hi * cs + lo * sn;
        if (tid < 64) {                      // k_new rotation pairs
            int rk = 4096 + h * DK + tid;
            float4 qlo = p4[rk * BATCH + b];
            float4 qhi = p4[(rk + 64) * BATCH + b];
            float klo = qlo.x + qlo.y + qlo.z + qlo.w;
            float khi = qhi.x + qhi.y + qhi.z + qhi.w;
            float inv2 = exp2f(-(float)tid * 0.2076205059304601f);
            float sn2, cs2;
            sincosf(fpos * inv2, &sn2, &cs2);
            kn[tid]      = klo * cs2 - khi * sn2;
            kn[tid + 64] = khi * cs2 + klo * sn2;
        } else if (tid < 192) {              // v_new
            int dv = tid - 64;
            float4 pv = p4[(5120 + h * DK + dv) * BATCH + b];
            vn[dv] = pv.x + pv.y + pv.z + pv.w;
        }
    }
    __syncthreads();

    const float4 q0 = *(const float4*)&qs[0 * DK + lane * 4];
    const float4 q1 = *(const float4*)&qs[1 * DK + lane * 4];
    const float4 q2 = *(const float4*)&qs[2 * DK + lane * 4];
    const float4 q3 = *(const float4*)&qs[3 * DK + lane * 4];

    const float scale = 0.08838834764831845f;
    float m_run = -INFINITY, l_run = 0.f;
    const int g2 = tid >> 6;
    const int d0 = (tid & 63) * 2;
    u64 o2 = 0ull;

    for (int ti = 0; ti < NT; ti++) {
        const int t0 = s0 + ti * TT;
        const int nv = min(s1 - t0, TT);
        const int buf = ti & 1;

        if (ti + 1 < NT) { KLOAD(kb); VISSUE((ti + 1) & 1); }
        if (ti + 2 < NT) TBL(ti + 2);
        if (ti + 1 < NT) CPWAIT(1); else CPWAIT(0);

        // substitute new-token V (pool slot holds stale data)
        int jp = pos - t0;
        if (jp >= 0 && jp < nv && tid < 32)
            *(float4*)&Vs[buf][jp][tid * 4] = *(const float4*)&vn[tid * 4];
        __syncthreads();

        // ---- scores (warp's 4 tokens, K from prefetched regs) ----
#pragma unroll
        for (int jj = 0; jj < 4; jj++) {
            int j = wid * 4 + jj;
            if (j < nv) {
                float4 kv = ka[jj];
                if (t0 + j == pos) kv = *(const float4*)&kn[lane * 4];
                float p0 = kv.x * q0.x + kv.y * q0.y + kv.z * q0.z + kv.w * q0.w;
                float p1 = kv.x * q1.x + kv.y * q1.y + kv.z * q1.z + kv.w * q1.w;
                float p2 = kv.x * q2.x + kv.y * q2.y + kv.z * q2.z + kv.w * q2.w;
                float p3 = kv.x * q3.x + kv.y * q3.y + kv.z * q3.z + kv.w * q3.w;
#pragma unroll
                for (int offv = 16; offv; offv >>= 1) {
                    p0 += __shfl_xor_sync(0xffffffffu, p0, offv);
                    p1 += __shfl_xor_sync(0xffffffffu, p1, offv);
                    p2 += __shfl_xor_sync(0xffffffffu, p2, offv);
                    p3 += __shfl_xor_sync(0xffffffffu, p3, offv);
                }
                if (lane == 0) {
                    ss[0][j] = p0 * scale;
                    ss[1][j] = p1 * scale;
                    ss[2][j] = p2 * scale;
                    ss[3][j] = p3 * scale;
                }
            }
        }
        __syncthreads();
        // ---- online softmax (warps 0..3, one per g) ----
        if (wid < 4) {
            int g = wid;
            float v0 = (lane < nv) ? ss[g][lane] : -INFINITY;
            float mt = v0;
#pragma unroll
            for (int offv = 16; offv; offv >>= 1)
                mt = fmaxf(mt, __shfl_xor_sync(0xffffffffu, mt, offv));
            float m_new = fmaxf(m_run, mt);
            float alpha = __expf(m_run - m_new);
            float e0 = __expf(v0 - m_new);
            psd[g][lane] = make_float2(e0, e0);
            float sum = e0;
#pragma unroll
            for (int offv = 16; offv; offv >>= 1)
                sum += __shfl_xor_sync(0xffffffffu, sum, offv);
            l_run = l_run * alpha + sum;
            m_run = m_new;
            if (lane == 0) salpha[g] = alpha;
        }
        __syncthreads();
        // ---- packed O accumulation ----
        {
            float a = salpha[g2];
            float2 ad = make_float2(a, a);
            u64 a2 = *(u64*)&ad;
            u64 t;
            MUL2(t, o2, a2);
            o2 = t;
#pragma unroll 4
            for (int j = 0; j < nv; j++) {
                u64 v = *(const u64*)&Vs[buf][j][d0];
                u64 p = *(const u64*)&psd[g2][j];
                FMA2(o2, p, v);
            }
        }
        __syncthreads();
#pragma unroll
        for (int jj = 0; jj < 4; jj++) ka[jj] = kb[jj];
    }

    const int pidx = (b * NKV + h) * SPLITS + split;
    float2 of = *(float2*)&o2;
    g_po[pidx * (GQ * DK) + g2 * DK + d0]     = of.x;
    g_po[pidx * (GQ * DK) + g2 * DK + d0 + 1] = of.y;
    if (wid < 4 && lane == 0) {
        g_pm[pidx * GQ + wid] = m_run;
        g_pl[pidx * GQ + wid] = l_run;
    }
    #undef TBL
    #undef KLOAD
    #undef VISSUE
}

// ============ combine split partials -> g_att (1 thread / elem) ==============
__global__ void combine_kernel()
{
    int id = blockIdx.x * 128 + threadIdx.x;   // 65536
    int d = id & 127;
    int g = (id >> 7) & 3;
    int h = (id >> 9) & 7;
    int b = id >> 12;
    int base = (b * NKV + h) * SPLITS;
    float M = -INFINITY;
#pragma unroll
    for (int s = 0; s < SPLITS; s++)
        M = fmaxf(M, g_pm[(base + s) * GQ + g]);
    float L = 0.f, o = 0.f;
#pragma unroll
    for (int s = 0; s < SPLITS; s++) {
        float e = __expf(g_pm[(base + s) * GQ + g] - M);
        L += g_pl[(base + s) * GQ + g] * e;
        o += e * g_po[(base + s) * (GQ * DK) + g * DK + d];
    }
    g_att[b * DMODEL + (h * GQ + g) * DK + d] = o / L;
}

// ============ reduce O partials -> d_out =====================================
__global__ void reduce_o(float* __restrict__ out)
{
    int id = blockIdx.x * 256 + threadIdx.x;   // 65536
    int b = id >> 12;
    int r = id & 4095;
    float4 v = ((const float4*)g_part_o)[r * BATCH + b];
    out[(size_t)b * DMODEL + r] = v.x + v.y + v.z + v.w;
}

// ---------------- host launcher ---------------------------------------------
extern "C" void kernel_launch(void* const* d_in, const int* in_sizes, int n_in,
                              void* d_out, int out_size)
{
    const float* hs = (const float*)d_in[0];
    const float* WQ = (const float*)d_in[1];
    const float* WK = (const float*)d_in[2];
    const float* WV = (const float*)d_in[3];
    const float* WO = (const float*)d_in[4];
    const float* kp = (const float*)d_in[5];
    const float* vp = (const float*)d_in[6];
    const int*   ps = (const int*)d_in[7];
    const int*   bt = (const int*)d_in[8];
    float* out = (float*)d_out;

    float *gatt, *partQ, *partO;
    cudaGetSymbolAddress((void**)&gatt,  g_att);
    cudaGetSymbolAddress((void**)&partQ, g_part_qkv);
    cudaGetSymbolAddress((void**)&partO, g_part_o);

    gemm_k<<<dim3(ROWS_QKV / RT, KSPLIT), 128>>>(WQ, WK, WV, hs, partQ);
    attn_kernel<<<dim3(SPLITS, NKV, BATCH), 256>>>(kp, vp, ps, bt);
    combine_kernel<<<512, 128>>>();
    gemm_k<<<dim3(ROWS_O / RT, KSPLIT), 128>>>(WO, WO, WO, gatt, partO);
    reduce_o<<<256, 256>>>(out);
}